// round 11
// baseline (speedup 1.0000x reference)
#include <cuda_runtime.h>
#include <math.h>

#define HH 512
#define WW 512
#define NB 32
#define NPIX (HH*WW)
#define EPSV 1e-8f
#define INV_A (1.0f/252004.0f)   // 1/(502*502)
#define STPITCH 656
#define SW(c) ((c) + 4*((c)>>4))
#define FNB 262144.0

// ---------------- static device storage --------------------------------------
__device__ float  g_yr[NB*NPIX];       // 32 MB real intermediate [b][j][i]
__device__ float  g_p1[NB][32][WW];
__device__ float  g_p2[NB][32][WW];
__device__ float  g_p3[NB][32][WW];
__device__ double g_tq1[32], g_tq2[32];
__device__ float  g_ccp[NB][64][121];  // per-block cc partials (no atomics)
__device__ float  g_nx[NB], g_ny[NB], g_corr[NB];
__device__ float2 g_phx[NB][512];      // PERMUTED: [q*32+t] = P[16*br5(t)+q]
__device__ float2 g_phy[NB][512];

// ---------------- f32x2 packed helpers ----------------------------------------
__device__ __forceinline__ unsigned long long packf2(float lo, float hi){
  unsigned long long r;
  asm("mov.b64 %0, {%1, %2};" : "=l"(r) : "f"(lo), "f"(hi));
  return r;
}
__device__ __forceinline__ float2 unpackf2(unsigned long long v){
  float2 r;
  asm("mov.b64 {%0, %1}, %2;" : "=f"(r.x), "=f"(r.y) : "l"(v));
  return r;
}
__device__ __forceinline__ void ffma2(unsigned long long &acc,
                                      unsigned long long a, unsigned long long b){
  asm("fma.rn.f32x2 %0, %1, %2, %0;" : "+l"(acc) : "l"(a), "l"(b));
}

// ---------------- complex helpers --------------------------------------------
__device__ __forceinline__ float2 cmulf(float2 a, float2 b){
  return make_float2(a.x*b.x - a.y*b.y, a.x*b.y + a.y*b.x);
}
__device__ __forceinline__ float2 caddf(float2 a, float2 b){ return make_float2(a.x+b.x, a.y+b.y); }
__device__ __forceinline__ float2 csubf(float2 a, float2 b){ return make_float2(a.x-b.x, a.y-b.y); }
__device__ __forceinline__ float2 mulnegi(float2 a){ return make_float2(a.y, -a.x); }

__device__ __forceinline__ void dft8(float2 a[8]){
  const float RT = 0.70710678118654752440f;
  float2 s0=caddf(a[0],a[4]), s1=caddf(a[1],a[5]), s2=caddf(a[2],a[6]), s3=caddf(a[3],a[7]);
  float2 d0=csubf(a[0],a[4]), d1=csubf(a[1],a[5]), d2=csubf(a[2],a[6]), d3=csubf(a[3],a[7]);
  d1 = cmulf(d1, make_float2( RT,-RT));
  d2 = mulnegi(d2);
  d3 = cmulf(d3, make_float2(-RT,-RT));
  float2 p0=caddf(s0,s2), p1=caddf(s1,s3), m0=csubf(s0,s2), m1=mulnegi(csubf(s1,s3));
  float2 q0=caddf(d0,d2), q1=caddf(d1,d3), n0=csubf(d0,d2), n1=mulnegi(csubf(d1,d3));
  a[0]=caddf(p0,p1); a[4]=csubf(p0,p1); a[2]=caddf(m0,m1); a[6]=csubf(m0,m1);
  a[1]=caddf(q0,q1); a[5]=csubf(q0,q1); a[3]=caddf(n0,n1); a[7]=csubf(n0,n1);
}

// DFT16 natural in/out
__device__ __forceinline__ void dft16(float2 d[16]){
  float2 e[8], o[8];
  #pragma unroll
  for (int j = 0; j < 8; j++){ e[j] = d[2*j]; o[j] = d[2*j+1]; }
  dft8(e); dft8(o);
  const float RT = 0.70710678118654752440f;
  const float C  = 0.92387953251128674f;
  const float S  = 0.38268343236508977f;
  const float2 w16[8] = {
    { 1.f, 0.f}, {  C, -S }, { RT, -RT}, {  S, -C },
    { 0.f,-1.f}, { -S, -C }, {-RT, -RT}, { -C, -S }
  };
  #pragma unroll
  for (int k = 0; k < 8; k++){
    float2 t = cmulf(w16[k], o[k]);
    d[k]   = caddf(e[k], t);
    d[k+8] = csubf(e[k], t);
  }
}

__device__ __forceinline__ float2 shfl_xor_f2(float2 v, int m){
  float2 r;
  r.x = __shfl_xor_sync(0xffffffffu, v.x, m);
  r.y = __shfl_xor_sync(0xffffffffu, v.y, m);
  return r;
}

// Forward 512-pt FFT, warp-resident. In d[r] = x[lane+32r]; out d[q] = X[16*br5(lane)+q].
__device__ __forceinline__ void warp_fft_fwd(float2 d[16], const float2 wq[16],
                                             const float2 cw[4], int lane){
  dft16(d);
  #pragma unroll
  for (int q = 1; q < 16; q++) d[q] = cmulf(d[q], wq[q]);
  #pragma unroll
  for (int si = 0; si < 5; si++){
    int L = 16 >> si;
    bool hi = (lane & L) != 0;
    float2 W = (si < 4) ? cw[si] : make_float2(1.f, 0.f);
    #pragma unroll
    for (int q = 0; q < 16; q++){
      float2 p = shfl_xor_f2(d[q], L);
      if (hi){
        float2 t = csubf(p, d[q]);
        d[q] = (si < 4) ? cmulf(t, W) : t;
      } else {
        d[q] = caddf(d[q], p);
      }
    }
  }
}

// Inverse-side forward DFT on scrambled input (see round-9 derivation).
__device__ __forceinline__ void warp_fft_inv(float2 d[16], const float2 wq[16],
                                             const float2 cw[4], int lane){
  #pragma unroll
  for (int si = 0; si < 5; si++){
    int L = 1 << si;
    bool hi = (lane & L) != 0;
    float2 W = (si > 0) ? cw[4 - si] : make_float2(1.f, 0.f);
    #pragma unroll
    for (int q = 0; q < 16; q++){
      float2 p = shfl_xor_f2(d[q], L);
      if (si > 0){
        if (hi) d[q] = csubf(p, cmulf(W, d[q]));
        else    d[q] = caddf(d[q], cmulf(W, p));
      } else {
        if (hi) d[q] = csubf(p, d[q]);
        else    d[q] = caddf(d[q], p);
      }
    }
  }
  #pragma unroll
  for (int q = 1; q < 16; q++) d[q] = cmulf(d[q], wq[q]);
  dft16(d);
}

__device__ __forceinline__ void setup_twiddles(float2 wq[16], float2 cw[4], int lane){
  float2 w1;
  sincospif(-(float)lane * (1.f/256.f), &w1.y, &w1.x);
  wq[0] = make_float2(1.f, 0.f);
  #pragma unroll
  for (int q = 1; q < 16; q++) wq[q] = cmulf(wq[q-1], w1);
  #pragma unroll
  for (int si = 0; si < 4; si++){
    int L = 16 >> si;
    sincospif(-(float)(lane & (L-1)) / (float)L, &cw[si].y, &cw[si].x);
  }
}

// ---------------- merged: cc (blocks 0..2047) + stats (blocks 2048..3103) -----
// cc: 192 thr = 6 warps; warp w handles dxi {w, w+6}; 8 frame rows per block.
// Packed FFMA2: even/odd-u lane pairs; template pairs pe (aligned) + po (packed).
__global__ void __launch_bounds__(192) k_main(const float* __restrict__ fr,
                                              const float* __restrict__ tpl){
  __shared__ float st[18*STPITCH];     // 46.1 KB
  __shared__ double tred1[6], tred2[6];
  int tid = threadIdx.x;

  if (blockIdx.x >= 2048){
    // ---------------- stats path ----------------
    int sidx = blockIdx.x - 2048;      // 0..1055
    int bb = sidx >> 5;                // 0..32
    int ry = sidx & 31;
    if (bb < NB){
      const float* xb = fr + (size_t)bb*NPIX + (size_t)ry*16*WW;
      for (int j = tid; j < 512; j += 192){
        float s1 = 0.f, s2 = 0.f, s3 = 0.f;
        #pragma unroll
        for (int i = 0; i < 16; i++){
          float v = xb[(size_t)i*WW + j];
          s1 += v; s2 = fmaf(v, v, s2);
          s3 += (i & 1) ? -v : v;
        }
        g_p1[bb][ry][j] = s1;
        g_p2[bb][ry][j] = s2;
        g_p3[bb][ry][j] = s3;
      }
    } else {
      const float* tb = tpl + (size_t)ry*16*WW;
      double s = 0.0, q = 0.0;
      for (int j = tid; j < 512; j += 192){
        #pragma unroll
        for (int i = 0; i < 16; i++){
          float v = tb[(size_t)i*WW + j];
          s += (double)v; q += (double)v*(double)v;
        }
      }
      #pragma unroll
      for (int o = 16; o; o >>= 1){
        s += __shfl_down_sync(0xffffffffu, s, o);
        q += __shfl_down_sync(0xffffffffu, q, o);
      }
      int lane = tid & 31, warp = tid / 32;
      if (lane == 0){ tred1[warp] = s; tred2[warp] = q; }
      __syncthreads();
      if (tid == 0){
        double S = 0.0, Q = 0.0;
        #pragma unroll
        for (int k = 0; k < 6; k++){ S += tred1[k]; Q += tred2[k]; }
        g_tq1[ry] = S; g_tq2[ry] = Q;
      }
    }
    return;
  }

  // ---------------- cc path ----------------
  int b    = blockIdx.x >> 6;
  int rblk = blockIdx.x & 63;
  int r0   = rblk * 8;
  for (int e = tid; e < 18*522; e += 192){
    int rr = e / 522, c = e - rr*522;
    int gi = (r0 - 5 + rr) & 511;
    int gj = (c - 5) & 511;
    st[rr*STPITCH + SW(c)] = tpl[gi*WW + gj] - 2.0f;
  }
  __syncthreads();
  int lane = tid & 31, warp = tid / 32;   // warp 0..5
  int nd = (warp == 5) ? 1 : 2;
  int j0 = lane * 16;
  unsigned long long acc2[2][11];
  #pragma unroll
  for (int s = 0; s < 2; s++)
    #pragma unroll
    for (int d = 0; d < 11; d++) acc2[s][d] = 0ull;

  const float* xbase = fr + ((size_t)b*512 + r0)*512 + j0;
  #pragma unroll 1
  for (int il = 0; il < 8; il++){
    float4 xq[4];
    #pragma unroll
    for (int k = 0; k < 4; k++)
      xq[k] = *reinterpret_cast<const float4*>(xbase + (size_t)il*512 + 4*k);
    unsigned long long xp[8];
    #pragma unroll
    for (int k = 0; k < 4; k++){
      xp[2*k]   = packf2(xq[k].x, xq[k].y);
      xp[2*k+1] = packf2(xq[k].z, xq[k].w);
    }
    #pragma unroll
    for (int s = 0; s < 2; s++){
      if (s < nd){
        int dxi = warp + 6*s;
        int trow = il - dxi + 10;          // in [0,17]
        const float* base = st + trow*STPITCH + 20*lane;
        float4 tq[7];
        #pragma unroll
        for (int k = 0; k < 4; k++) tq[k] = *reinterpret_cast<const float4*>(base + 4*k);
        #pragma unroll
        for (int k = 0; k < 3; k++) tq[4+k] = *reinterpret_cast<const float4*>(base + 20 + 4*k);
        float tv[28];
        #pragma unroll
        for (int k = 0; k < 7; k++){
          int o = (k < 4) ? 4*k : 16 + 4*(k-4);
          tv[o]=tq[k].x; tv[o+1]=tq[k].y; tv[o+2]=tq[k].z; tv[o+3]=tq[k].w;
        }
        unsigned long long pe[13], po[12];
        #pragma unroll
        for (int m = 0; m < 13; m++) pe[m] = packf2(tv[2*m],   tv[2*m+1]);
        #pragma unroll
        for (int m = 0; m < 12; m++) po[m] = packf2(tv[2*m+1], tv[2*m+2]);
        // even d: acc2[d] += (x2p,x2p1)*(tv[2p+10-d],tv[2p+11-d]) = xp[p]*pe[p+(10-d)/2]
        #pragma unroll
        for (int d = 0; d < 11; d += 2){
          int m0 = (10 - d) >> 1;
          #pragma unroll
          for (int p = 0; p < 8; p++) ffma2(acc2[s][d], xp[p], pe[p + m0]);
        }
        #pragma unroll
        for (int d = 1; d < 11; d += 2){
          int m0 = (9 - d) >> 1;
          #pragma unroll
          for (int p = 0; p < 8; p++) ffma2(acc2[s][d], xp[p], po[p + m0]);
        }
      }
    }
  }
  // cross-lane reduce, one dxi row per (warp, s)
  #pragma unroll
  for (int s = 0; s < 2; s++){
    if (s < nd){
      int dxi = warp + 6*s;
      #pragma unroll
      for (int d = 0; d < 11; d++){
        float2 v = unpackf2(acc2[s][d]);
        float sum = v.x + v.y;
        #pragma unroll
        for (int o = 16; o; o >>= 1) sum += __shfl_down_sync(0xffffffffu, sum, o);
        if (lane == 0) g_ccp[b][rblk][dxi*11 + d] = sum;
      }
    }
  }
}

// ---------------- bands + denom + cc-combine + argmax + parabola + phases -----
__global__ void __launch_bounds__(512) k_shiftphase(const float* __restrict__ fr){
  __shared__ float sb1[11][512];
  __shared__ float sb2[11][512];
  __shared__ float part1[242], part2[242];
  __shared__ float ncc[121];
  __shared__ float wp1[16], wp2[16];
  __shared__ float s_shx, s_shy, s_fm, s_T;
  __shared__ double s_tm, s_tvar;
  int b = blockIdx.x, t = threadIdx.x;
  if (t == 0){
    double S = 0.0, Q = 0.0;
    #pragma unroll
    for (int k = 0; k < 32; k++){ S += g_tq1[k]; Q += g_tq2[k]; }
    double tm = S / FNB;
    s_tm = tm;
    s_tvar = Q - FNB*tm*tm;
  }
  float s1 = 0.f, s2 = 0.f, s3 = 0.f;
  #pragma unroll
  for (int ry = 0; ry < 32; ry++){
    s1 += g_p1[b][ry][t]; s2 += g_p2[b][ry][t]; s3 += g_p3[b][ry][t];
  }
  const float* xb = fr + (size_t)b*NPIX;
  float topv[10], botv[10];
  #pragma unroll
  for (int i = 0; i < 10; i++) topv[i] = xb[(size_t)i*WW + t];
  #pragma unroll
  for (int i = 0; i < 10; i++) botv[i] = xb[(size_t)(502+i)*WW + t];
  float bs1[11], bs2[11];
  bs1[10] = 0.f; bs2[10] = 0.f;
  #pragma unroll
  for (int m = 9; m >= 0; m--){
    bs1[m] = bs1[m+1] + botv[m];
    bs2[m] = bs2[m+1] + botv[m]*botv[m];
  }
  float tp1 = 0.f, tp2 = 0.f;
  #pragma unroll
  for (int p = 0; p < 11; p++){
    sb1[p][t] = s1 - tp1 - bs1[p];
    sb2[p][t] = s2 - tp2 - bs2[p];
    if (p < 10){ tp1 += topv[p]; tp2 += topv[p]*topv[p]; }
  }
  float rsum = s1;
  float csum = (t & 1) ? -s3 : s3;
  #pragma unroll
  for (int o = 16; o; o >>= 1){
    rsum += __shfl_down_sync(0xffffffffu, rsum, o);
    csum += __shfl_down_sync(0xffffffffu, csum, o);
  }
  if ((t & 31) == 0){ wp1[t>>5] = rsum; wp2[t>>5] = csum; }
  __syncthreads();
  if (t == 0){
    float a = 0.f, c = 0.f;
    #pragma unroll
    for (int k = 0; k < 16; k++){ a += wp1[k]; c += wp2[k]; }
    s_fm = a / (float)NPIX;
    s_T = c;
  }
  if (t < 242){
    int w = t >> 1, s = t & 1;
    int p = w / 11, q = w - 11*p;
    int j0 = q + 251*s;
    float a = 0.f, c = 0.f;
    for (int j = j0; j < j0 + 251; j++){ a += sb1[p][j]; c += sb2[p][j]; }
    part1[t] = a; part2[t] = c;
  }
  __syncthreads();
  if (t < 121){
    float w1 = part1[2*t] + part1[2*t+1];
    float w2 = part2[2*t] + part2[2*t+1];
    float ls  = w1 * INV_A;
    float lsq = w2 * INV_A;
    float var = lsq - ls*ls*INV_A + EPSV;
    if (var < 0.f) var = 0.f;
    float den = sqrtf(((float)s_tvar + EPSV) * var);
    float ccs = 0.f;
    for (int k = 0; k < 64; k++) ccs += g_ccp[b][k][t];
    double corr = (double)s_fm * FNB * (s_tm - 2.0);
    float num = fabsf((float)((double)ccs - corr));
    float v = num / den;
    if (isnan(v)) v = 0.f;
    ncc[t] = v;
  }
  __syncthreads();
  if (t == 0){
    float best = -1e30f; int am = 0;
    for (int k = 0; k < 121; k++){ if (ncc[k] > best){ best = ncc[k]; am = k; } }
    int xi = am / 11, yi = am % 11;
    float shx = -(float)(xi - 5);
    float shy = -(float)(yi - 5);
    int xm = xi - 1; if (xm < 0) xm += 11;   // jnp negative index wraps
    int xp = xi + 1; if (xp > 10) xp = 10;   // jnp OOB gather clamps
    int ym = yi - 1; if (ym < 0) ym += 11;
    int yp = yi + 1; if (yp > 10) yp = 10;
    float l0  = logf(ncc[xi*11 + yi]);
    float lxm = logf(ncc[xm*11 + yi]);
    float lxp = logf(ncc[xp*11 + yi]);
    float lym = logf(ncc[xi*11 + ym]);
    float lyp = logf(ncc[xi*11 + yp]);
    shx -= (lxm - lxp) / (2.f*lxm - 4.f*l0 + 2.f*lxp);
    shy -= (lym - lyp) / (2.f*lym - 4.f*l0 + 2.f*lyp);
    s_shx = shx; s_shy = shy;
    float nx = sinpif(shx), ny = sinpif(shy);
    g_nx[b] = nx; g_ny[b] = ny;
    g_corr[b] = nx * ny * s_T * (1.f/262144.f);
  }
  __syncthreads();
  // permuted phase tables: slot t = q*32 + lt holds P[16*br5(lt)+q]
  {
    int q = t >> 5, lt = t & 31;
    int k = 16 * (int)(__brev((unsigned)lt) >> 27) + q;
    float nr = (k < 256) ? (float)k : (float)(k - 512);
    float2 py, px;
    sincospif(-s_shy * nr * (1.f/256.f), &py.y, &py.x);
    sincospif(-s_shx * nr * (1.f/256.f), &px.y, &px.x);
    g_phy[b][t] = py;
    g_phx[b][t] = px;
  }
}

// ---------------- pass 1: warp FFT, 2 packed rows/warp, transposed output -----
__global__ void __launch_bounds__(128) k_pass1(const float* __restrict__ fr){
  __shared__ float2 sst[4][520];
  int tid = threadIdx.x;
  int w    = tid >> 5;
  int lane = tid & 31;
  int bi = blockIdx.x;             // 0..2047
  int b  = bi >> 6;
  int i0 = (bi & 63) * 8;
  const float* p1 = fr + ((size_t)b*512 + i0 + 2*w) * 512;
  const float* p2 = p1 + 512;
  const float2* ph = &g_phy[b][0];
  float ny = g_ny[b];
  float sg = (lane & 1) ? -1.f : 1.f;      // (-1)^n, n = lane+32v

  float2 wq[16], cw[4];
  setup_twiddles(wq, cw, lane);

  float2 d[16];
  #pragma unroll
  for (int r = 0; r < 16; r++)
    d[r] = make_float2(p1[lane + 32*r], p2[lane + 32*r]);

  warp_fft_fwd(d, wq, cw, lane);           // d[q] = V[16*br5(lane)+q]
  float2 V256;
  V256.x = __shfl_sync(0xffffffffu, d[0].x, 1);
  V256.y = __shfl_sync(0xffffffffu, d[0].y, 1);
  float b1 = ny * V256.x * (1.f/512.f);
  float b2 = ny * V256.y * (1.f/512.f);
  #pragma unroll
  for (int q = 0; q < 16; q++){
    float2 p = ph[q*32 + lane];
    float xr = d[q].x*p.x - d[q].y*p.y;
    float xi = d[q].x*p.y + d[q].y*p.x;
    d[q] = make_float2(xr * (1.f/512.f), -xi * (1.f/512.f));   // conj + scale
  }
  warp_fft_inv(d, wq, cw, lane);           // d[v] = conj(u)[lane+32v]
  #pragma unroll
  for (int v = 0; v < 16; v++){
    int n = lane + 32*v;
    sst[w][n + (n>>6)] = make_float2(d[v].x + sg*b2, -d[v].y - sg*b1);
  }
  __syncthreads();
  for (int idx = tid; idx < 512; idx += 128){
    int e = idx + (idx>>6);
    float2 v0 = sst[0][e], v1 = sst[1][e], v2 = sst[2][e], v3 = sst[3][e];
    float4* op = reinterpret_cast<float4*>(g_yr + ((size_t)b*512 + idx)*512 + i0);
    op[0] = make_float4(v0.x, v0.y, v1.x, v1.y);
    op[1] = make_float4(v2.x, v2.y, v3.x, v3.y);
  }
}

// ---------------- pass 2: warp FFT, 2 packed columns/warp, final output -------
__global__ void __launch_bounds__(128) k_pass2(float* __restrict__ out){
  int tid = threadIdx.x;
  int w    = tid >> 5;
  int lane = tid & 31;
  int bi = blockIdx.x;             // 0..2047
  int b  = bi >> 6;
  int j1 = (bi & 63) * 8 + 2*w;    // even column
  const float* c1 = g_yr + ((size_t)b*512 + j1) * 512;
  const float* c2 = c1 + 512;
  const float2* ph = &g_phx[b][0];
  float nx = g_nx[b];
  float corr = g_corr[b];
  float sg = (lane & 1) ? -1.f : 1.f;

  float2 wq[16], cw[4];
  setup_twiddles(wq, cw, lane);

  float2 d[16];
  #pragma unroll
  for (int r = 0; r < 16; r++)
    d[r] = make_float2(c1[lane + 32*r], c2[lane + 32*r]);

  warp_fft_fwd(d, wq, cw, lane);           // U
  float2 U256;
  U256.x = __shfl_sync(0xffffffffu, d[0].x, 1);
  U256.y = __shfl_sync(0xffffffffu, d[0].y, 1);
  float e1 = nx * U256.x * (1.f/512.f) - corr;
  float e2 = nx * U256.y * (1.f/512.f) - corr;
  #pragma unroll
  for (int q = 0; q < 16; q++){
    float2 p = ph[q*32 + lane];
    float xr = d[q].x*p.x - d[q].y*p.y;
    float xi = d[q].x*p.y + d[q].y*p.x;
    d[q] = make_float2(xr * (1.f/512.f), -xi * (1.f/512.f));
  }
  warp_fft_inv(d, wq, cw, lane);
  float* r1 = out + ((size_t)b*512 + j1) * 512;
  float* r2 = r1 + 512;
  #pragma unroll
  for (int v = 0; v < 16; v++){
    int n = lane + 32*v;
    r1[n] = d[v].x + sg*e2;
    r2[n] = -d[v].y - sg*e1;
  }
}

// ---------------- launcher -----------------------------------------------------
extern "C" void kernel_launch(void* const* d_in, const int* in_sizes, int n_in,
                              void* d_out, int out_size){
  const float* fr  = (const float*)d_in[0];
  const float* tpl = (const float*)d_in[1];
  if (n_in >= 2 && in_sizes[0] < in_sizes[1]){
    fr  = (const float*)d_in[1];
    tpl = (const float*)d_in[0];
  }
  float* out = (float*)d_out;
  k_main<<<2048 + 1056, 192>>>(fr, tpl);
  k_shiftphase<<<32, 512>>>(fr);
  k_pass1<<<2048, 128>>>(fr);
  k_pass2<<<2048, 128>>>(out);
}

// round 12
// speedup vs baseline: 1.1175x; 1.1175x over previous
#include <cuda_runtime.h>
#include <math.h>

#define HH 512
#define WW 512
#define NB 32
#define NPIX (HH*WW)
#define EPSV 1e-8f
#define INV_A (1.0f/252004.0f)   // 1/(502*502)
#define STPITCH 656
#define SW(c) ((c) + 4*((c)>>4))
#define FNB 262144.0

// ---------------- static device storage --------------------------------------
__device__ float  g_yr[NB*NPIX];       // 32 MB real intermediate [b][j][i]
__device__ float  g_p1[NB][32][WW];
__device__ float  g_p2[NB][32][WW];
__device__ float  g_p3[NB][32][WW];
__device__ double g_tq1[32], g_tq2[32];
__device__ float  g_ccp[NB][64][121];  // per-block cc partials (no atomics)
__device__ float  g_nx[NB], g_ny[NB], g_corr[NB];
__device__ float2 g_phx[NB][512];      // PERMUTED: [q*32+t] = P[16*br5(t)+q]
__device__ float2 g_phy[NB][512];

// ---------------- complex helpers --------------------------------------------
__device__ __forceinline__ float2 cmulf(float2 a, float2 b){
  return make_float2(a.x*b.x - a.y*b.y, a.x*b.y + a.y*b.x);
}
__device__ __forceinline__ float2 caddf(float2 a, float2 b){ return make_float2(a.x+b.x, a.y+b.y); }
__device__ __forceinline__ float2 csubf(float2 a, float2 b){ return make_float2(a.x-b.x, a.y-b.y); }
__device__ __forceinline__ float2 mulnegi(float2 a){ return make_float2(a.y, -a.x); }

__device__ __forceinline__ void dft8(float2 a[8]){
  const float RT = 0.70710678118654752440f;
  float2 s0=caddf(a[0],a[4]), s1=caddf(a[1],a[5]), s2=caddf(a[2],a[6]), s3=caddf(a[3],a[7]);
  float2 d0=csubf(a[0],a[4]), d1=csubf(a[1],a[5]), d2=csubf(a[2],a[6]), d3=csubf(a[3],a[7]);
  d1 = cmulf(d1, make_float2( RT,-RT));
  d2 = mulnegi(d2);
  d3 = cmulf(d3, make_float2(-RT,-RT));
  float2 p0=caddf(s0,s2), p1=caddf(s1,s3), m0=csubf(s0,s2), m1=mulnegi(csubf(s1,s3));
  float2 q0=caddf(d0,d2), q1=caddf(d1,d3), n0=csubf(d0,d2), n1=mulnegi(csubf(d1,d3));
  a[0]=caddf(p0,p1); a[4]=csubf(p0,p1); a[2]=caddf(m0,m1); a[6]=csubf(m0,m1);
  a[1]=caddf(q0,q1); a[5]=csubf(q0,q1); a[3]=caddf(n0,n1); a[7]=csubf(n0,n1);
}

// DFT16 natural in/out
__device__ __forceinline__ void dft16(float2 d[16]){
  float2 e[8], o[8];
  #pragma unroll
  for (int j = 0; j < 8; j++){ e[j] = d[2*j]; o[j] = d[2*j+1]; }
  dft8(e); dft8(o);
  const float RT = 0.70710678118654752440f;
  const float C  = 0.92387953251128674f;
  const float S  = 0.38268343236508977f;
  const float2 w16[8] = {
    { 1.f, 0.f}, {  C, -S }, { RT, -RT}, {  S, -C },
    { 0.f,-1.f}, { -S, -C }, {-RT, -RT}, { -C, -S }
  };
  #pragma unroll
  for (int k = 0; k < 8; k++){
    float2 t = cmulf(w16[k], o[k]);
    d[k]   = caddf(e[k], t);
    d[k+8] = csubf(e[k], t);
  }
}

__device__ __forceinline__ float2 shfl_xor_f2(float2 v, int m){
  float2 r;
  r.x = __shfl_xor_sync(0xffffffffu, v.x, m);
  r.y = __shfl_xor_sync(0xffffffffu, v.y, m);
  return r;
}

// Forward 512-pt FFT, warp-resident. In d[r] = x[lane+32r]; out d[q] = X[16*br5(lane)+q].
__device__ __forceinline__ void warp_fft_fwd(float2 d[16], const float2 wq[16],
                                             const float2 cw[4], int lane){
  dft16(d);
  #pragma unroll
  for (int q = 1; q < 16; q++) d[q] = cmulf(d[q], wq[q]);
  #pragma unroll
  for (int si = 0; si < 5; si++){
    int L = 16 >> si;
    bool hi = (lane & L) != 0;
    float2 W = (si < 4) ? cw[si] : make_float2(1.f, 0.f);
    #pragma unroll
    for (int q = 0; q < 16; q++){
      float2 p = shfl_xor_f2(d[q], L);
      if (hi){
        float2 t = csubf(p, d[q]);
        d[q] = (si < 4) ? cmulf(t, W) : t;
      } else {
        d[q] = caddf(d[q], p);
      }
    }
  }
}

// Inverse-side forward DFT on scrambled input (round-9 derivation).
__device__ __forceinline__ void warp_fft_inv(float2 d[16], const float2 wq[16],
                                             const float2 cw[4], int lane){
  #pragma unroll
  for (int si = 0; si < 5; si++){
    int L = 1 << si;
    bool hi = (lane & L) != 0;
    float2 W = (si > 0) ? cw[4 - si] : make_float2(1.f, 0.f);
    #pragma unroll
    for (int q = 0; q < 16; q++){
      float2 p = shfl_xor_f2(d[q], L);
      if (si > 0){
        if (hi) d[q] = csubf(p, cmulf(W, d[q]));
        else    d[q] = caddf(d[q], cmulf(W, p));
      } else {
        if (hi) d[q] = csubf(p, d[q]);
        else    d[q] = caddf(d[q], p);
      }
    }
  }
  #pragma unroll
  for (int q = 1; q < 16; q++) d[q] = cmulf(d[q], wq[q]);
  dft16(d);
}

__device__ __forceinline__ void setup_twiddles(float2 wq[16], float2 cw[4], int lane){
  float2 w1;
  sincospif(-(float)lane * (1.f/256.f), &w1.y, &w1.x);
  wq[0] = make_float2(1.f, 0.f);
  #pragma unroll
  for (int q = 1; q < 16; q++) wq[q] = cmulf(wq[q-1], w1);
  #pragma unroll
  for (int si = 0; si < 4; si++){
    int L = 16 >> si;
    sincospif(-(float)(lane & (L-1)) / (float)L, &cw[si].y, &cw[si].x);
  }
}

// ---------------- merged: cc (blocks 0..2047) + stats (blocks 2048..3103) -----
// cc path = round-10 scalar version verbatim (128 thr, 4 warps, dxi {w,w+4,w+8}).
__global__ void __launch_bounds__(128) k_main(const float* __restrict__ fr,
                                              const float* __restrict__ tpl){
  __shared__ float st[18*STPITCH];     // 46.1 KB (reused as reduce scratch)
  int tid = threadIdx.x;               // 128

  if (blockIdx.x >= 2048){
    // ---------------- stats path ----------------
    int sidx = blockIdx.x - 2048;      // 0..1055
    int bb = sidx >> 5;                // 0..32
    int ry = sidx & 31;
    if (bb < NB){
      const float* xb = fr + (size_t)bb*NPIX + (size_t)ry*16*WW;
      #pragma unroll
      for (int jj = 0; jj < 4; jj++){
        int j = tid + 128*jj;
        float s1 = 0.f, s2 = 0.f, s3 = 0.f;
        #pragma unroll
        for (int i = 0; i < 16; i++){
          float v = xb[(size_t)i*WW + j];
          s1 += v; s2 = fmaf(v, v, s2);
          s3 += (i & 1) ? -v : v;
        }
        g_p1[bb][ry][j] = s1;
        g_p2[bb][ry][j] = s2;
        g_p3[bb][ry][j] = s3;
      }
    } else {
      const float* tb = tpl + (size_t)ry*16*WW;
      double s = 0.0, q = 0.0;
      #pragma unroll
      for (int jj = 0; jj < 4; jj++){
        int j = tid + 128*jj;
        #pragma unroll
        for (int i = 0; i < 16; i++){
          float v = tb[(size_t)i*WW + j];
          s += (double)v; q += (double)v*(double)v;
        }
      }
      #pragma unroll
      for (int o = 16; o; o >>= 1){
        s += __shfl_down_sync(0xffffffffu, s, o);
        q += __shfl_down_sync(0xffffffffu, q, o);
      }
      __shared__ double tr1[4], tr2[4];
      int lane = tid & 31, warp = tid >> 5;
      if (lane == 0){ tr1[warp] = s; tr2[warp] = q; }
      __syncthreads();
      if (tid == 0){
        g_tq1[ry] = tr1[0] + tr1[1] + tr1[2] + tr1[3];
        g_tq2[ry] = tr2[0] + tr2[1] + tr2[2] + tr2[3];
      }
    }
    return;
  }

  // ---------------- cc path (round-10 scalar) ----------------
  int b    = blockIdx.x >> 6;
  int rblk = blockIdx.x & 63;
  int r0   = rblk * 8;
  for (int e = tid; e < 18*522; e += 128){
    int rr = e / 522, c = e - rr*522;
    int gi = (r0 - 5 + rr) & 511;
    int gj = (c - 5) & 511;
    st[rr*STPITCH + SW(c)] = tpl[gi*WW + gj] - 2.0f;
  }
  __syncthreads();
  int lane = tid & 31, warp = tid >> 5;
  int nd = (warp == 3) ? 2 : 3;
  int j0 = lane * 16;
  float acc[3][11];
  #pragma unroll
  for (int s = 0; s < 3; s++)
    #pragma unroll
    for (int d = 0; d < 11; d++) acc[s][d] = 0.f;
  const float* xbase = fr + ((size_t)b*512 + r0)*512 + j0;
  #pragma unroll 1
  for (int il = 0; il < 8; il++){
    float4 xq[4];
    #pragma unroll
    for (int k = 0; k < 4; k++)
      xq[k] = *reinterpret_cast<const float4*>(xbase + (size_t)il*512 + 4*k);
    float xv[16];
    #pragma unroll
    for (int k = 0; k < 4; k++){ xv[4*k]=xq[k].x; xv[4*k+1]=xq[k].y; xv[4*k+2]=xq[k].z; xv[4*k+3]=xq[k].w; }
    #pragma unroll
    for (int s = 0; s < 3; s++){
      if (s < nd){
        int dxi = warp + 4*s;
        int trow = il - dxi + 10;          // in [0,17]
        const float* base = st + trow*STPITCH + 20*lane;
        float4 tq[7];
        #pragma unroll
        for (int k = 0; k < 4; k++) tq[k] = *reinterpret_cast<const float4*>(base + 4*k);
        #pragma unroll
        for (int k = 0; k < 3; k++) tq[4+k] = *reinterpret_cast<const float4*>(base + 20 + 4*k);
        float tv[28];
        #pragma unroll
        for (int k = 0; k < 7; k++){
          int o = (k < 4) ? 4*k : 16 + 4*(k-4);
          tv[o]=tq[k].x; tv[o+1]=tq[k].y; tv[o+2]=tq[k].z; tv[o+3]=tq[k].w;
        }
        #pragma unroll
        for (int d = 0; d < 11; d++)
          #pragma unroll
          for (int u = 0; u < 16; u++)
            acc[s][d] = fmaf(xv[u], tv[u + 10 - d], acc[s][d]);
      }
    }
  }
  __syncthreads();
  float* red = st + warp * (32*37);
  #pragma unroll
  for (int k = 0; k < 33; k++)
    red[lane*37 + k] = acc[k/11][k - (k/11)*11];
  __syncwarp();
  #pragma unroll
  for (int rnd = 0; rnd < 2; rnd++){
    int L = lane + 32*rnd;
    if (L < nd*11){
      float s = 0.f;
      #pragma unroll
      for (int l = 0; l < 32; l++) s += red[l*37 + L];
      int dxi = warp + 4*(L/11);
      g_ccp[b][rblk][dxi*11 + (L - (L/11)*11)] = s;
    }
  }
}

// ---------------- bands + denom + cc-combine + argmax + parabola + phases -----
__global__ void __launch_bounds__(512) k_shiftphase(const float* __restrict__ fr){
  __shared__ float sb1[11][512];
  __shared__ float sb2[11][512];
  __shared__ float part1[242], part2[242];
  __shared__ float ncc[121];
  __shared__ float wp1[16], wp2[16];
  __shared__ float s_shx, s_shy, s_fm, s_T;
  __shared__ double s_tm, s_tvar;
  int b = blockIdx.x, t = threadIdx.x;
  if (t == 0){
    double S = 0.0, Q = 0.0;
    #pragma unroll
    for (int k = 0; k < 32; k++){ S += g_tq1[k]; Q += g_tq2[k]; }
    double tm = S / FNB;
    s_tm = tm;
    s_tvar = Q - FNB*tm*tm;
  }
  float s1 = 0.f, s2 = 0.f, s3 = 0.f;
  #pragma unroll
  for (int ry = 0; ry < 32; ry++){
    s1 += g_p1[b][ry][t]; s2 += g_p2[b][ry][t]; s3 += g_p3[b][ry][t];
  }
  const float* xb = fr + (size_t)b*NPIX;
  float topv[10], botv[10];
  #pragma unroll
  for (int i = 0; i < 10; i++) topv[i] = xb[(size_t)i*WW + t];
  #pragma unroll
  for (int i = 0; i < 10; i++) botv[i] = xb[(size_t)(502+i)*WW + t];
  float bs1[11], bs2[11];
  bs1[10] = 0.f; bs2[10] = 0.f;
  #pragma unroll
  for (int m = 9; m >= 0; m--){
    bs1[m] = bs1[m+1] + botv[m];
    bs2[m] = bs2[m+1] + botv[m]*botv[m];
  }
  float tp1 = 0.f, tp2 = 0.f;
  #pragma unroll
  for (int p = 0; p < 11; p++){
    sb1[p][t] = s1 - tp1 - bs1[p];
    sb2[p][t] = s2 - tp2 - bs2[p];
    if (p < 10){ tp1 += topv[p]; tp2 += topv[p]*topv[p]; }
  }
  float rsum = s1;
  float csum = (t & 1) ? -s3 : s3;
  #pragma unroll
  for (int o = 16; o; o >>= 1){
    rsum += __shfl_down_sync(0xffffffffu, rsum, o);
    csum += __shfl_down_sync(0xffffffffu, csum, o);
  }
  if ((t & 31) == 0){ wp1[t>>5] = rsum; wp2[t>>5] = csum; }
  __syncthreads();
  if (t == 0){
    float a = 0.f, c = 0.f;
    #pragma unroll
    for (int k = 0; k < 16; k++){ a += wp1[k]; c += wp2[k]; }
    s_fm = a / (float)NPIX;
    s_T = c;
  }
  if (t < 242){
    int w = t >> 1, s = t & 1;
    int p = w / 11, q = w - 11*p;
    int j0 = q + 251*s;
    float a = 0.f, c = 0.f;
    for (int j = j0; j < j0 + 251; j++){ a += sb1[p][j]; c += sb2[p][j]; }
    part1[t] = a; part2[t] = c;
  }
  __syncthreads();
  if (t < 121){
    float w1 = part1[2*t] + part1[2*t+1];
    float w2 = part2[2*t] + part2[2*t+1];
    float ls  = w1 * INV_A;
    float lsq = w2 * INV_A;
    float var = lsq - ls*ls*INV_A + EPSV;
    if (var < 0.f) var = 0.f;
    float den = sqrtf(((float)s_tvar + EPSV) * var);
    float ccs = 0.f;
    for (int k = 0; k < 64; k++) ccs += g_ccp[b][k][t];
    double corr = (double)s_fm * FNB * (s_tm - 2.0);
    float num = fabsf((float)((double)ccs - corr));
    float v = num / den;
    if (isnan(v)) v = 0.f;
    ncc[t] = v;
  }
  __syncthreads();
  if (t == 0){
    float best = -1e30f; int am = 0;
    for (int k = 0; k < 121; k++){ if (ncc[k] > best){ best = ncc[k]; am = k; } }
    int xi = am / 11, yi = am % 11;
    float shx = -(float)(xi - 5);
    float shy = -(float)(yi - 5);
    int xm = xi - 1; if (xm < 0) xm += 11;   // jnp negative index wraps
    int xp = xi + 1; if (xp > 10) xp = 10;   // jnp OOB gather clamps
    int ym = yi - 1; if (ym < 0) ym += 11;
    int yp = yi + 1; if (yp > 10) yp = 10;
    float l0  = logf(ncc[xi*11 + yi]);
    float lxm = logf(ncc[xm*11 + yi]);
    float lxp = logf(ncc[xp*11 + yi]);
    float lym = logf(ncc[xi*11 + ym]);
    float lyp = logf(ncc[xi*11 + yp]);
    shx -= (lxm - lxp) / (2.f*lxm - 4.f*l0 + 2.f*lxp);
    shy -= (lym - lyp) / (2.f*lym - 4.f*l0 + 2.f*lyp);
    s_shx = shx; s_shy = shy;
    float nx = sinpif(shx), ny = sinpif(shy);
    g_nx[b] = nx; g_ny[b] = ny;
    g_corr[b] = nx * ny * s_T * (1.f/262144.f);
  }
  __syncthreads();
  // permuted phase tables: slot t = q*32 + lt holds P[16*br5(lt)+q]
  {
    int q = t >> 5, lt = t & 31;
    int k = 16 * (int)(__brev((unsigned)lt) >> 27) + q;
    float nr = (k < 256) ? (float)k : (float)(k - 512);
    float2 py, px;
    sincospif(-s_shy * nr * (1.f/256.f), &py.y, &py.x);
    sincospif(-s_shx * nr * (1.f/256.f), &px.y, &px.x);
    g_phy[b][t] = py;
    g_phx[b][t] = px;
  }
}

// ---------------- pass 1: warp FFT, 2 packed rows/warp, transposed output -----
__global__ void __launch_bounds__(128) k_pass1(const float* __restrict__ fr){
  __shared__ float2 sst[4][520];
  int tid = threadIdx.x;
  int w    = tid >> 5;
  int lane = tid & 31;
  int bi = blockIdx.x;             // 0..2047
  int b  = bi >> 6;
  int i0 = (bi & 63) * 8;
  const float* p1 = fr + ((size_t)b*512 + i0 + 2*w) * 512;
  const float* p2 = p1 + 512;
  const float2* ph = &g_phy[b][0];
  float ny = g_ny[b];
  float sg = (lane & 1) ? -1.f : 1.f;      // (-1)^n, n = lane+32v

  float2 wq[16], cw[4];
  setup_twiddles(wq, cw, lane);

  float2 d[16];
  #pragma unroll
  for (int r = 0; r < 16; r++)
    d[r] = make_float2(p1[lane + 32*r], p2[lane + 32*r]);

  warp_fft_fwd(d, wq, cw, lane);           // d[q] = V[16*br5(lane)+q]
  float2 V256;
  V256.x = __shfl_sync(0xffffffffu, d[0].x, 1);
  V256.y = __shfl_sync(0xffffffffu, d[0].y, 1);
  float b1 = ny * V256.x * (1.f/512.f);
  float b2 = ny * V256.y * (1.f/512.f);
  #pragma unroll
  for (int q = 0; q < 16; q++){
    float2 p = ph[q*32 + lane];
    float xr = d[q].x*p.x - d[q].y*p.y;
    float xi = d[q].x*p.y + d[q].y*p.x;
    d[q] = make_float2(xr * (1.f/512.f), -xi * (1.f/512.f));   // conj + scale
  }
  warp_fft_inv(d, wq, cw, lane);           // d[v] = conj(u)[lane+32v]
  #pragma unroll
  for (int v = 0; v < 16; v++){
    int n = lane + 32*v;
    sst[w][n + (n>>6)] = make_float2(d[v].x + sg*b2, -d[v].y - sg*b1);
  }
  __syncthreads();
  for (int idx = tid; idx < 512; idx += 128){
    int e = idx + (idx>>6);
    float2 v0 = sst[0][e], v1 = sst[1][e], v2 = sst[2][e], v3 = sst[3][e];
    float4* op = reinterpret_cast<float4*>(g_yr + ((size_t)b*512 + idx)*512 + i0);
    op[0] = make_float4(v0.x, v0.y, v1.x, v1.y);
    op[1] = make_float4(v2.x, v2.y, v3.x, v3.y);
  }
}

// ---------------- pass 2: warp FFT, 2 packed columns/warp, final output -------
__global__ void __launch_bounds__(128) k_pass2(float* __restrict__ out){
  int tid = threadIdx.x;
  int w    = tid >> 5;
  int lane = tid & 31;
  int bi = blockIdx.x;             // 0..2047
  int b  = bi >> 6;
  int j1 = (bi & 63) * 8 + 2*w;    // even column
  const float* c1 = g_yr + ((size_t)b*512 + j1) * 512;
  const float* c2 = c1 + 512;
  const float2* ph = &g_phx[b][0];
  float nx = g_nx[b];
  float corr = g_corr[b];
  float sg = (lane & 1) ? -1.f : 1.f;

  float2 wq[16], cw[4];
  setup_twiddles(wq, cw, lane);

  float2 d[16];
  #pragma unroll
  for (int r = 0; r < 16; r++)
    d[r] = make_float2(c1[lane + 32*r], c2[lane + 32*r]);

  warp_fft_fwd(d, wq, cw, lane);           // U
  float2 U256;
  U256.x = __shfl_sync(0xffffffffu, d[0].x, 1);
  U256.y = __shfl_sync(0xffffffffu, d[0].y, 1);
  float e1 = nx * U256.x * (1.f/512.f) - corr;
  float e2 = nx * U256.y * (1.f/512.f) - corr;
  #pragma unroll
  for (int q = 0; q < 16; q++){
    float2 p = ph[q*32 + lane];
    float xr = d[q].x*p.x - d[q].y*p.y;
    float xi = d[q].x*p.y + d[q].y*p.x;
    d[q] = make_float2(xr * (1.f/512.f), -xi * (1.f/512.f));
  }
  warp_fft_inv(d, wq, cw, lane);
  float* r1 = out + ((size_t)b*512 + j1) * 512;
  float* r2 = r1 + 512;
  #pragma unroll
  for (int v = 0; v < 16; v++){
    int n = lane + 32*v;
    r1[n] = d[v].x + sg*e2;
    r2[n] = -d[v].y - sg*e1;
  }
}

// ---------------- launcher -----------------------------------------------------
extern "C" void kernel_launch(void* const* d_in, const int* in_sizes, int n_in,
                              void* d_out, int out_size){
  const float* fr  = (const float*)d_in[0];
  const float* tpl = (const float*)d_in[1];
  if (n_in >= 2 && in_sizes[0] < in_sizes[1]){
    fr  = (const float*)d_in[1];
    tpl = (const float*)d_in[0];
  }
  float* out = (float*)d_out;
  k_main<<<2048 + 1056, 128>>>(fr, tpl);
  k_shiftphase<<<32, 512>>>(fr);
  k_pass1<<<2048, 128>>>(fr);
  k_pass2<<<2048, 128>>>(out);
}